// round 11
// baseline (speedup 1.0000x reference)
#include <cuda_runtime.h>
#include <cstdint>

// HolographicFMLayer: batched all-pairs circular convolution.
// inputs: float32 [B, 24, 64]  ->  out: float32 [B, 276, 64]
// out[b,p,n] = sum_k x[b,i,k] * x[b,j,(n-k) mod 64], pairs = triu_indices(24, k=1)
//
// CRT split: x^64-1 = (x^16-1)(x^16+1)(x^32+1)
//   per field: u = lo+hi, v = (lo-hi)/sqrt2; P=(u_lo+u_hi)/2, Q=(u_lo-u_hi)/2
//   per pair : d1 = cyclic16(P), d2 = negacyclic16(Q), c2 = negacyclic32(v)
//   recon    : c1[n<16]=d1+d2, c1[16..31]=d1-d2; out[n<32]=c1+c2, out[n+32]=c1-c2
// 1536 FMA/pair (vs 4096 direct). 2 threads/pair (role split).
//
// R10: scalar STATIC ROTATION window. R7's scalar shifts were materialized as
// ~15 MOVs/iter under the 56-reg cap (issue-count forensics: 1720 vs 840
// ideal issues/warp). Fixed slots + compile-time rotated indices
// w[(q-k)&15] eliminate all copies: 1 slot rebuilt per iter via 1 LDS.
// (R5's rotation failed only because packed rebuilds split register pairs;
// scalar slots have no such cost.)

#define NF 24
#define NPAIR 276
#define LEN 64
#define THREADS 192
#define PAIRS_PER_BLOCK 92      // 3 blocks per batch
#define ACTIVE (PAIRS_PER_BLOCK * 2)
#define SV 65                   // 64-entry rows: 65 mod 32 == 1
#define SP 33                   // 32-entry rows: 33 mod 32 == 1
#define OFF_P (NF * SV)                 // 1560
#define OFF_Q (OFF_P + NF * SP + 24)    // +24 pad: (OFF_Q-OFF_P) mod 32 == 16
#define SMEM_FLOATS (OFF_Q + NF * SP)

// constexpr-built triu pair table in constant memory
struct PairTab { unsigned short ij[NPAIR]; };  // i*32 + j
static constexpr PairTab make_tab() {
    PairTab t{};
    int p = 0;
    for (int i = 0; i < NF; ++i)
        for (int j = i + 1; j < NF; ++j) { t.ij[p] = (unsigned short)(i * 32 + j); ++p; }
    return t;
}
__constant__ PairTab TAB = make_tab();

// Partial length-N convolution, 16 consecutive outputs starting at QOFF:
//   acc[q] = out[QOFF+q] = sum_{k=0}^{N-1} A[k+N] * B[QOFF+q-k+N]
// Static rotation invariant: at iter k, slot s holds B[QOFF+N-k+((s+k)&15)],
// so pair q reads w[(q-k)&15] (constant index after unroll). After iter k,
// slot (15-k)&15 is rebuilt with B[QOFF+N-1-k]. One LDS, zero copies.
template <int N, int QOFF>
__device__ __forceinline__ void conv16rot(const float* __restrict__ A,
                                          const float* __restrict__ B,
                                          float* __restrict__ acc)
{
    float w[16];
#pragma unroll
    for (int s = 0; s < 16; ++s) w[s] = B[QOFF + N + s];

    // k = 0 peeled as mul (no acc zero-init)
    {
        const float a = A[N];
#pragma unroll
        for (int q = 0; q < 16; ++q) acc[q] = a * w[q];
        w[15] = B[QOFF + N - 1];
    }
#pragma unroll
    for (int k = 1; k < N; ++k) {
        const float a = A[N + k];
#pragma unroll
        for (int q = 0; q < 16; ++q)
            acc[q] = fmaf(a, w[(q - k) & 15], acc[q]);
        if (k < N - 1)
            w[(15 - k) & 15] = B[QOFF + N - 1 - k];
    }
}

__global__ __launch_bounds__(THREADS, 6)
void holo_rot_kernel(const float* __restrict__ in, float* __restrict__ out)
{
    __shared__ float smem[SMEM_FLOATS];
    float* __restrict__ bufV = smem;           // negacyclic-32 operand, scale 1/sqrt2
    float* __restrict__ bufP = smem + OFF_P;   // cyclic-16 operand (dup), scale 1/2
    float* __restrict__ bufQ = smem + OFF_Q;   // negacyclic-16 operand, scale 1/2

    const int batch = blockIdx.x;
    const float* __restrict__ src = in + (size_t)batch * (NF * LEN);
    const int tid = threadIdx.x;

    // ---- per-field folds ----
    for (int idx = tid; idx < NF * 16; idx += THREADS) {
        const int f = idx >> 4, m = idx & 15;
        const float* x = src + f * LEN;
        const float x0 = x[m], x1 = x[m + 16], x2 = x[m + 32], x3 = x[m + 48];
        const float s = 0.70710678118654752f;
        const float vlo = (x0 - x2) * s, vhi = (x1 - x3) * s;
        const float ulo = x0 + x2,       uhi = x1 + x3;
        const float P = (ulo + uhi) * 0.5f, Q = (ulo - uhi) * 0.5f;
        float* bV = bufV + f * SV;
        bV[m]      = -vlo;  bV[m + 16] = -vhi;
        bV[m + 32] =  vlo;  bV[m + 48] =  vhi;
        float* bP = bufP + f * SP;
        bP[m] = P;  bP[m + 16] = P;
        float* bQ = bufQ + f * SP;
        bQ[m] = -Q; bQ[m + 16] = Q;
    }
    __syncthreads();

    const int role = tid & 1;                          // lanes 2p, 2p+1 share a pair
    int p = blockIdx.y * PAIRS_PER_BLOCK + (tid >> 1);
    const bool live = (tid < ACTIVE);
    if (p >= NPAIR) p = NPAIR - 1;                     // tail threads duplicate, no store
    const int ij = TAB.ij[p];
    const int i  = ij >> 5;
    const int j  = ij & 31;

    // ---- phase 1: one 16-conv each (role0: cyclic P, role1: negacyclic Q) ----
    const float* A16 = (role ? bufQ : bufP) + i * SP;
    const float* B16 = (role ? bufQ : bufP) + j * SP;
    float d[16];
    conv16rot<16, 0>(A16, B16, d);                     // d[q] = d_role[q]

    // exchange between role threads (adjacent lanes), fold into c1
    // role0: c1[n] = d1+d2 (n = q);  role1: c1[n] = d1-d2 (n = 16+q)
    float c1[16];
#pragma unroll
    for (int q = 0; q < 16; ++q) {
        const float other = __shfl_xor_sync(0xFFFFFFFFu, d[q], 1);
        c1[q] = role ? (other - d[q]) : (d[q] + other);
    }

    // ---- phase 2: negacyclic-32, 16 outputs per role ----
    const float* A32 = bufV + i * SV;
    const float* B32 = bufV + j * SV;
    float av[16];
    if (role == 0) conv16rot<32, 0 >(A32, B32, av);    // av[q] = c2[q]
    else           conv16rot<32, 16>(A32, B32, av);    // av[q] = c2[16+q]

    // ---- reconstruct & store ----
    if (live) {
        const int base = role << 4;  // 0 or 16
        float4* __restrict__ dst =
            (float4*)(out + ((size_t)batch * NPAIR + p) * LEN + base);
#pragma unroll
        for (int g = 0; g < 4; ++g) {
            dst[g] = make_float4(c1[4*g+0] + av[4*g+0], c1[4*g+1] + av[4*g+1],
                                 c1[4*g+2] + av[4*g+2], c1[4*g+3] + av[4*g+3]);
            dst[g + 8] = make_float4(c1[4*g+0] - av[4*g+0], c1[4*g+1] - av[4*g+1],
                                     c1[4*g+2] - av[4*g+2], c1[4*g+3] - av[4*g+3]);
        }
    }
}

extern "C" void kernel_launch(void* const* d_in, const int* in_sizes, int n_in,
                              void* d_out, int out_size)
{
    const float* in  = (const float*)d_in[0];
    float*       out = (float*)d_out;
    const int batches = in_sizes[0] / (NF * LEN);   // 2048 for the bench shape
    dim3 grid(batches, 3);
    holo_rot_kernel<<<grid, THREADS>>>(in, out);
}